// round 17
// baseline (speedup 1.0000x reference)
#include <cuda_runtime.h>
#include <cuda_bf16.h>
#include <math.h>
#include <stdint.h>

#define NS 19200   // T*H*W
#define TT 12
#define HH 40
#define WW 40
#define CC 128

// Scratch (device globals)
__device__ float    g_inv[NS];           // per-position inv-norm * sqrt(C)
__device__ uint32_t g_q[NS * 64];        // q rows, bf16x2, pre-scaled by C^-0.5
__device__ uint32_t g_k[NS * 64];        // k rows, bf16x2
__device__ uint32_t g_v[NS * 64];        // v rows, bf16x2
__device__ uint32_t g_wqkv[384 * 64];    // qkv_w bf16x2
__device__ uint32_t g_wproj[128 * 64];   // proj_w bf16x2

__device__ __forceinline__ void mma_bf16(float* c, const uint32_t* a, const uint32_t* b) {
    asm volatile(
        "mma.sync.aligned.m16n8k16.row.col.f32.bf16.bf16.f32 "
        "{%0,%1,%2,%3}, {%4,%5,%6,%7}, {%8,%9}, {%0,%1,%2,%3};\n"
        : "+f"(c[0]), "+f"(c[1]), "+f"(c[2]), "+f"(c[3])
        : "r"(a[0]), "r"(a[1]), "r"(a[2]), "r"(a[3]), "r"(b[0]), "r"(b[1]));
}

__device__ __forceinline__ uint32_t pack_bf16(float x, float y) {
    uint32_t r;
    asm("cvt.rn.bf16x2.f32 %0, %1, %2;" : "=r"(r) : "f"(y), "f"(x));  // lo=x, hi=y
    return r;
}

__device__ __forceinline__ void cp8(uint32_t dst, const void* src) {
    asm volatile("cp.async.ca.shared.global [%0], [%1], 8;" :: "r"(dst), "l"(src));
}
__device__ __forceinline__ void cp16(uint32_t dst, const void* src) {
    asm volatile("cp.async.ca.shared.global [%0], [%1], 16;" :: "r"(dst), "l"(src));
}

// ---------------------------------------------------------------------------
// Kernel 0: weight prep, fp32 -> bf16x2
// ---------------------------------------------------------------------------
__global__ void prep_w(const float* __restrict__ qkv_w, const float* __restrict__ proj_w) {
    int i = blockIdx.x * blockDim.x + threadIdx.x;   // 0 .. 32767
    if (i < 384 * 64) {
        float2 v = *(const float2*)(qkv_w + i * 2);
        g_wqkv[i] = pack_bf16(v.x, v.y);
    } else {
        int j = i - 384 * 64;
        float2 v = *(const float2*)(proj_w + j * 2);
        g_wproj[j] = pack_bf16(v.x, v.y);
    }
}

// ---------------------------------------------------------------------------
// Kernel 1: per-position inv norm (round-15 winner)
// ---------------------------------------------------------------------------
__global__ void inv_kernel(const float* __restrict__ x) {
    int s = blockIdx.x * blockDim.x + threadIdx.x;
    if (s >= NS) return;
    float ss = 0.f;
#pragma unroll 16
    for (int c = 0; c < CC; c++) {
        float v = x[(size_t)c * NS + s];
        ss = fmaf(v, v, ss);
    }
    g_inv[s] = 11.313708498984761f / fmaxf(sqrtf(ss), 1e-12f);
}

// ---------------------------------------------------------------------------
// GEMM common bits
// ---------------------------------------------------------------------------
#define LDU 68
#define A_U (64 * LDU)
#define B128_U (128 * LDU)

__device__ __forceinline__ void gemm_core(const uint32_t* As, const uint32_t* Bs,
                                          int wm, int wn, int g, int tg,
                                          float acc[2][4][4]) {
#pragma unroll
    for (int ks = 0; ks < 8; ks++) {
        int kb = ks * 8;
        uint32_t af[2][4], bf[4][2];
#pragma unroll
        for (int mt = 0; mt < 2; mt++) {
            int m = wm * 32 + mt * 16 + g;
            af[mt][0] = As[m * LDU + kb + tg];
            af[mt][1] = As[(m + 8) * LDU + kb + tg];
            af[mt][2] = As[m * LDU + kb + tg + 4];
            af[mt][3] = As[(m + 8) * LDU + kb + tg + 4];
        }
#pragma unroll
        for (int nt = 0; nt < 4; nt++) {
            int n = wn * 32 + nt * 8 + g;
            bf[nt][0] = Bs[n * LDU + kb + tg];
            bf[nt][1] = Bs[n * LDU + kb + tg + 4];
        }
#pragma unroll
        for (int mt = 0; mt < 2; mt++)
#pragma unroll
            for (int nt = 0; nt < 4; nt++)
                mma_bf16(acc[mt][nt], af[mt], bf[nt]);
    }
}

// ---------------------------------------------------------------------------
// Kernel 2: qkv GEMM (round-10..15 winner, unchanged)
// ---------------------------------------------------------------------------
#define QKV_SMEM ((A_U + B128_U) * 4)   // 52224 B
static_assert(QKV_SMEM <= 227 * 1024, "qkv smem");

__global__ void __launch_bounds__(256, 2)
gemm_qkv(const float* __restrict__ x, const float* __restrict__ gamma,
         const float* __restrict__ bias) {
    extern __shared__ uint32_t su[];
    uint32_t* As = su;
    uint32_t* Bs = su + A_U;

    int tid = threadIdx.x;
    int lane = tid & 31;
    int warp = tid >> 5;
    int wm = warp & 1, wn = warp >> 1;
    int g = lane >> 2, tg = lane & 3;
    int bx = blockIdx.x, by = blockIdx.y;

#pragma unroll
    for (int i = 0; i < 8; i++) {
        int id = tid + i * 256;
        int r = id >> 5, c4 = (id & 31) << 2;
        int row = by * 64 + r;
        int ch = row / 150;
        int s = (row - ch * 150) * 128 + c4;
        float gm = __ldg(&gamma[ch]);
        float4 iv = *(const float4*)(g_inv + s);
        float4 v = *(const float4*)(x + (size_t)row * 128 + c4);
        v.x *= iv.x * gm; v.y *= iv.y * gm; v.z *= iv.z * gm; v.w *= iv.w * gm;
        As[r * LDU + (c4 >> 1)]     = pack_bf16(v.x, v.y);
        As[r * LDU + (c4 >> 1) + 1] = pack_bf16(v.z, v.w);
    }
    const uint32_t* Bbase = g_wqkv + (size_t)bx * 128 * 64;
#pragma unroll
    for (int i = 0; i < 8; i++) {
        int id = tid + i * 256;
        int r = id >> 4, c = (id & 15) * 4;
        uint4 v = *(const uint4*)(Bbase + r * 64 + c);
        *(uint4*)(Bs + r * LDU + c) = v;
    }
    __syncthreads();

    float acc[2][4][4];
#pragma unroll
    for (int i = 0; i < 2; i++)
#pragma unroll
        for (int j = 0; j < 4; j++)
#pragma unroll
            for (int e = 0; e < 4; e++) acc[i][j][e] = 0.f;

    gemm_core(As, Bs, wm, wn, g, tg, acc);

    const float QS = 0.08838834764831845f;
    uint32_t* dst = (bx == 0) ? g_q : (bx == 1) ? g_k : g_v;
    float sc = (bx == 0) ? QS : 1.0f;
#pragma unroll
    for (int nt = 0; nt < 4; nt++) {
        int nloc = wn * 32 + nt * 8 + 2 * tg;
        float2 bb = *(const float2*)(bias + bx * 128 + nloc);
#pragma unroll
        for (int mt = 0; mt < 2; mt++) {
            int row0 = by * 64 + wm * 32 + mt * 16 + g;
            dst[row0 * 64 + (nloc >> 1)] =
                pack_bf16((acc[mt][nt][0] + bb.x) * sc, (acc[mt][nt][1] + bb.y) * sc);
            dst[(row0 + 8) * 64 + (nloc >> 1)] =
                pack_bf16((acc[mt][nt][2] + bb.x) * sc, (acc[mt][nt][3] + bb.y) * sc);
        }
    }
}

// ---------------------------------------------------------------------------
// Kernel 3: FUSED neighborhood attention + output projection.
// 16 positions/CTA, 512 threads. Phases:
//   0: cp.async k/v/q (group A) + proj_w (group B) + sl/sc/pp tables
//   1: score mma (12 n-tiles)                  [wait A]
//   2: softmax
//   3: AV -> att row (bf16) into qsm (q is dead)
//   4: proj mma (16 n-tiles, warp w = tile w)  [wait B]
//   5: epilogue: + proj_b + resid(x) -> out fp32
// ---------------------------------------------------------------------------
#define VPAD 66    // u32 stride for v rows
#define SCW 104    // scall row stride (floats)

__global__ void __launch_bounds__(512)
attn_proj_kernel(const float* __restrict__ rpb, const float* __restrict__ resid,
                 const float* __restrict__ pbias, float* __restrict__ outArg) {
    extern __shared__ uint32_t smu[];
    uint32_t* qsm   = smu;                        // [16][LDU]  q, then att
    uint32_t* ksm   = qsm + 16 * LDU;             // [96][LDU]
    uint32_t* vsm   = ksm + 96 * LDU;             // [96][VPAD]
    uint32_t* pwsm  = vsm + 96 * VPAD;            // [128][LDU] proj_w
    float*    scall = (float*)(pwsm + B128_U);    // [16][SCW]
    float*    sc    = scall + 16 * SCW;           // [16][32] bias
    float*    aw    = sc + 512;                   // [16][32] weights
    int*      sl    = (int*)(aw + 512);           // [16][32] slots
    int*      pp    = sl + 512;                   // [16] position flat index

    int tid = threadIdx.x, lane = tid & 31, warp = tid >> 5;   // warp 0..15
    int g = lane >> 2, tg = lane & 3;
    int w0 = blockIdx.x * 4, h0 = blockIdx.y * 2, t0 = blockIdx.z * 2;

    int tlo = min(max(t0 - 1, 0), TT - 3);
    int hlo = min(max(h0 - 1, 0), HH - 3);
    int wlo = min(max(w0 - 1, 0), WW - 3);

    int j = warp;
    int pt = t0 + (j >> 3), ph = h0 + ((j >> 2) & 1), pw = w0 + (j & 3);
    int p  = (pt * HH + ph) * WW + pw;

    // phase 0a: group A = q + k/v staging
    uint32_t qs_b = (uint32_t)__cvta_generic_to_shared(qsm);
    uint32_t ks_b = (uint32_t)__cvta_generic_to_shared(ksm);
    uint32_t vs_b = (uint32_t)__cvta_generic_to_shared(vsm);
    uint32_t pw_b = (uint32_t)__cvta_generic_to_shared(pwsm);
    cp8(qs_b + (j * LDU + lane * 2) * 4, g_q + p * 64 + lane * 2);
#pragma unroll
    for (int i = 0; i < 6; i++) {
        int rowid = warp + i * 16;
        int dt = rowid / 24, rrem = rowid % 24;
        int dh = rrem / 6, dw = rrem % 6;
        int nt = min(tlo + dt, TT - 1);
        int nh = min(hlo + dh, HH - 1);
        int nw = min(wlo + dw, WW - 1);
        int base = ((nt * HH + nh) * WW + nw) * 64 + lane * 2;
        cp8(ks_b + (rowid * LDU + lane * 2) * 4, g_k + base);
        cp8(vs_b + (rowid * VPAD + lane * 2) * 4, g_v + base);
    }
    asm volatile("cp.async.commit_group;");

    // phase 0b: group B = proj_w staging (has the whole attn span to land)
#pragma unroll
    for (int i = 0; i < 4; i++) {
        int id = tid + i * 512;
        int r = id >> 4, c = (id & 15) * 4;
        cp16(pw_b + (r * LDU + c) * 4, g_wproj + r * 64 + c);
    }
    asm volatile("cp.async.commit_group;");

    // phase 0c: tables while staging flies
    if (tid < 16) {
        int qt = t0 + (tid >> 3), qh = h0 + ((tid >> 2) & 1), qw = w0 + (tid & 3);
        pp[tid] = (qt * HH + qh) * WW + qw;
    }
    if (tid < 432) {
        int jj = tid / 27, n = tid % 27;
        int qt = t0 + (jj >> 3), qh = h0 + ((jj >> 2) & 1), qw = w0 + (jj & 3);
        int dt = n / 9, dh = (n / 3) % 3, dw = n % 3;
        int stt = min(max(qt - 1, 0), TT - 3);
        int sh  = min(max(qh - 1, 0), HH - 3);
        int sw  = min(max(qw - 1, 0), WW - 3);
        int nt = stt + dt, nh = sh + dh, nw = sw + dw;
        sl[jj * 32 + n] = ((nt - tlo) * 4 + (nh - hlo)) * 6 + (nw - wlo);
        int bt = nt - qt + 2, bh = nh - qh + 2, bw = nw - qw + 2;
        sc[jj * 32 + n] = __ldg(&rpb[(bt * 5 + bh) * 5 + bw]);
    }
    asm volatile("cp.async.wait_group 1;");   // group A done (pw may still fly)
    __syncthreads();

    // phase 1: score mma — 12 n-tiles, warp w does tile w (w < 12)
    if (warp < 12) {
        uint32_t af[8][4];
#pragma unroll
        for (int ks = 0; ks < 8; ks++) {
            int kb = ks * 8;
            af[ks][0] = qsm[g * LDU + kb + tg];
            af[ks][1] = qsm[(g + 8) * LDU + kb + tg];
            af[ks][2] = qsm[g * LDU + kb + tg + 4];
            af[ks][3] = qsm[(g + 8) * LDU + kb + tg + 4];
        }
        float a4[4] = {0.f, 0.f, 0.f, 0.f};
        int n = warp * 8 + g;
#pragma unroll
        for (int ks = 0; ks < 8; ks++) {
            int kb = ks * 8;
            uint32_t bf[2];
            bf[0] = ksm[n * LDU + kb + tg];
            bf[1] = ksm[n * LDU + kb + tg + 4];
            mma_bf16(a4, af[ks], bf);
        }
        *(float2*)(scall + g * SCW + warp * 8 + 2 * tg) = make_float2(a4[0], a4[1]);
        *(float2*)(scall + (g + 8) * SCW + warp * 8 + 2 * tg) = make_float2(a4[2], a4[3]);
    }
    __syncthreads();   // scores ready; qsm is now dead (att goes there)

    // phase 2: softmax — warp j, position j
    {
        float s = -1e30f;
        if (lane < 27)
            s = sc[j * 32 + lane] + scall[j * SCW + sl[j * 32 + lane]];
        float m = s;
#pragma unroll
        for (int o = 16; o; o >>= 1) m = fmaxf(m, __shfl_xor_sync(0xffffffffu, m, o));
        float e = (lane < 27) ? __expf(s - m) : 0.f;
        float den = e;
#pragma unroll
        for (int o = 16; o; o >>= 1) den += __shfl_xor_sync(0xffffffffu, den, o);
        aw[j * 32 + lane] = e / den;
    }
    __syncwarp();

    // phase 3: AV — warp j, position j; att row (bf16) into qsm
    {
        float4 acc = {0.f, 0.f, 0.f, 0.f};
#pragma unroll
        for (int n = 0; n < 27; n++) {
            float a = aw[j * 32 + n];
            int slot = sl[j * 32 + n];
            uint2 vv = *(const uint2*)(vsm + slot * VPAD + lane * 2);
            float2 f0 = __bfloat1622float2(*(const __nv_bfloat162*)&vv.x);
            float2 f1 = __bfloat1622float2(*(const __nv_bfloat162*)&vv.y);
            acc.x = fmaf(a, f0.x, acc.x);
            acc.y = fmaf(a, f0.y, acc.y);
            acc.z = fmaf(a, f1.x, acc.z);
            acc.w = fmaf(a, f1.y, acc.w);
        }
        uint2 o = { pack_bf16(acc.x, acc.y), pack_bf16(acc.z, acc.w) };
        *(uint2*)(qsm + j * LDU + lane * 2) = o;
    }
    asm volatile("cp.async.wait_group 0;");   // proj_w resident
    __syncthreads();                           // all att rows visible

    // phase 4: proj mma — att(16x128) @ proj_w(128x128)^T; warp w = n-tile w
    {
        uint32_t af[8][4];
#pragma unroll
        for (int ks = 0; ks < 8; ks++) {
            int kb = ks * 8;
            af[ks][0] = qsm[g * LDU + kb + tg];
            af[ks][1] = qsm[(g + 8) * LDU + kb + tg];
            af[ks][2] = qsm[g * LDU + kb + tg + 4];
            af[ks][3] = qsm[(g + 8) * LDU + kb + tg + 4];
        }
        float a4[4] = {0.f, 0.f, 0.f, 0.f};
        int n = warp * 8 + g;
#pragma unroll
        for (int ks = 0; ks < 8; ks++) {
            int kb = ks * 8;
            uint32_t bf[2];
            bf[0] = pwsm[n * LDU + kb + tg];
            bf[1] = pwsm[n * LDU + kb + tg + 4];
            mma_bf16(a4, af[ks], bf);
        }
        // phase 5: epilogue — rows g and g+8, cols n0 = warp*8 + 2tg
        int n0 = warp * 8 + 2 * tg;
        float2 bb = *(const float2*)(pbias + n0);
        int pg  = pp[g];
        int pg8 = pp[g + 8];
        float2 r0 = *(const float2*)(resid + (size_t)pg * 128 + n0);
        float2 r1 = *(const float2*)(resid + (size_t)pg8 * 128 + n0);
        float2 o0 = { a4[0] + bb.x + r0.x, a4[1] + bb.y + r0.y };
        float2 o1 = { a4[2] + bb.x + r1.x, a4[3] + bb.y + r1.y };
        *(float2*)(outArg + (size_t)pg * 128 + n0)  = o0;
        *(float2*)(outArg + (size_t)pg8 * 128 + n0) = o1;
    }
}

static const int ATTN_SMEM =
    (16 * LDU + 96 * LDU + 96 * VPAD + B128_U + 16 * SCW + 512 * 3 + 16) * 4;  // 103488 B
static_assert((16 * LDU + 96 * LDU + 96 * VPAD + B128_U + 16 * SCW + 512 * 3 + 16) * 4
              <= 227 * 1024, "attn smem");

// ---------------------------------------------------------------------------
extern "C" void kernel_launch(void* const* d_in, const int* in_sizes, int n_in,
                              void* d_out, int out_size) {
    const float* x      = (const float*)d_in[0];
    const float* gamma  = (const float*)d_in[1];
    const float* qkv_w  = (const float*)d_in[2];
    const float* qkv_b  = (const float*)d_in[3];
    const float* rpb    = (const float*)d_in[4];
    const float* proj_w = (const float*)d_in[5];
    const float* proj_b = (const float*)d_in[6];
    float* out = (float*)d_out;

    cudaFuncSetAttribute(attn_proj_kernel, cudaFuncAttributeMaxDynamicSharedMemorySize, ATTN_SMEM);
    cudaFuncSetAttribute(gemm_qkv, cudaFuncAttributeMaxDynamicSharedMemorySize, QKV_SMEM);

    prep_w<<<128, 256>>>(qkv_w, proj_w);
    inv_kernel<<<(NS + 255) / 256, 256>>>(x);
    gemm_qkv<<<dim3(3, NS / 64), 256, QKV_SMEM>>>(x, gamma, qkv_b);
    attn_proj_kernel<<<dim3(WW / 4, HH / 2, TT / 2), 512, ATTN_SMEM>>>(rpb, x, proj_b, out);
}